// round 13
// baseline (speedup 1.0000x reference)
#include <cuda_runtime.h>

#define B_  16
#define T_  1024
#define D_  1024
#define HS_ 64
#define H_  16
#define M_  (B_*T_)   // 16384

typedef unsigned long long u64_t;

// ---- packed f32x2 helpers ----
__device__ __forceinline__ u64_t pack_dup(float v) {
    u64_t r; unsigned u = __float_as_uint(v);
    asm("mov.b64 %0, {%1, %1};" : "=l"(r) : "r"(u));
    return r;
}
__device__ __forceinline__ void fma2(u64_t &d, u64_t a, u64_t b) {
    asm("fma.rn.f32x2 %0, %1, %2, %0;" : "+l"(d) : "l"(a), "l"(b));
}
__device__ __forceinline__ void mul2(u64_t &d, u64_t a) {
    asm("mul.rn.f32x2 %0, %0, %1;" : "+l"(d) : "l"(a));
}
__device__ __forceinline__ void unpack2(u64_t v, float &lo, float &hi) {
    unsigned a, b;
    asm("mov.b64 {%0, %1}, %2;" : "=r"(a), "=r"(b) : "l"(v));
    lo = __uint_as_float(a); hi = __uint_as_float(b);
}

union F4U2 { float4 f4; u64_t u2[2]; };
#define COMP(v,kk) ((kk)==0?(v).x:(kk)==1?(v).y:(kk)==2?(v).z:(v).w)

// Scratch (device globals — no allocation allowed)
__device__ float g_q [M_*HS_];
__device__ float g_k [M_*HS_];
__device__ float g_v [M_*HS_];
__device__ float g_ho[M_*HS_];
__device__ float g_wp[HS_*D_];

// ---------------------------------------------------------------------------
// Fold Wp: Wp_eff[j][e] = sum_h Wp[h*HS+j][e]
// ---------------------------------------------------------------------------
__global__ void fold_wp_kernel(const float* __restrict__ Wp) {
    int idx = blockIdx.x * blockDim.x + threadIdx.x;
    int j = idx >> 10;
    int e = idx & 1023;
    float s = 0.f;
    #pragma unroll
    for (int h = 0; h < H_; ++h) s += Wp[(h*HS_ + j)*D_ + e];
    g_wp[idx] = s;
    (void)e; (void)j;
}

// ---------------------------------------------------------------------------
// Fused QKV projection, software-pipelined, FFMA2, vectorized smem reads.
// A read as float4 per 4 k-steps; B read as float4 per k (reinterpret 2xu64).
// ---------------------------------------------------------------------------
__global__ void __launch_bounds__(256)
qkv_gemm_kernel(const float* __restrict__ x,
                const float* __restrict__ Wq,
                const float* __restrict__ Wk,
                const float* __restrict__ Wv) {
    const int BM = 64, BK = 32;
    __shared__ float As [BM][36];     // 36: 16B-aligned float4 rows
    __shared__ float Wqs[BK][HS_];
    __shared__ float Wks[BK][HS_];
    __shared__ float Wvs[BK][HS_];

    int tid = threadIdx.x;
    int tx  = tid & 15, ty = tid >> 4;
    int row0 = blockIdx.x * BM;

    const int ar0 = (tid      ) >> 3, ac0 = (tid      ) & 7;
    const int ar1 = (tid + 256) >> 3, ac1 = (tid + 256) & 7;
    const int wr0 = (tid      ) >> 4, wc0 = (tid      ) & 15;
    const int wr1 = (tid + 256) >> 4, wc1 = (tid + 256) & 15;

    u64_t aq2[4][2] = {}, ak2[4][2] = {}, av2[4][2] = {};

    float4 pa0, pa1, pq0, pq1, pk0, pk1, pv0, pv1;
    {
        pa0 = *(const float4*)&x[(size_t)(row0 + ar0)*D_ + ac0*4];
        pa1 = *(const float4*)&x[(size_t)(row0 + ar1)*D_ + ac1*4];
        size_t o0 = (size_t)wr0*HS_ + wc0*4;
        size_t o1 = (size_t)wr1*HS_ + wc1*4;
        pq0 = *(const float4*)&Wq[o0]; pq1 = *(const float4*)&Wq[o1];
        pk0 = *(const float4*)&Wk[o0]; pk1 = *(const float4*)&Wk[o1];
        pv0 = *(const float4*)&Wv[o0]; pv1 = *(const float4*)&Wv[o1];
    }

    for (int k0 = 0; k0 < D_; k0 += BK) {
        *(float4*)&As[ar0][ac0*4] = pa0;
        *(float4*)&As[ar1][ac1*4] = pa1;
        *(float4*)&Wqs[wr0][wc0*4] = pq0; *(float4*)&Wqs[wr1][wc1*4] = pq1;
        *(float4*)&Wks[wr0][wc0*4] = pk0; *(float4*)&Wks[wr1][wc1*4] = pk1;
        *(float4*)&Wvs[wr0][wc0*4] = pv0; *(float4*)&Wvs[wr1][wc1*4] = pv1;
        __syncthreads();

        int kn = k0 + BK;
        if (kn < D_) {
            pa0 = *(const float4*)&x[(size_t)(row0 + ar0)*D_ + kn + ac0*4];
            pa1 = *(const float4*)&x[(size_t)(row0 + ar1)*D_ + kn + ac1*4];
            size_t o0 = (size_t)(kn + wr0)*HS_ + wc0*4;
            size_t o1 = (size_t)(kn + wr1)*HS_ + wc1*4;
            pq0 = *(const float4*)&Wq[o0]; pq1 = *(const float4*)&Wq[o1];
            pk0 = *(const float4*)&Wk[o0]; pk1 = *(const float4*)&Wk[o1];
            pv0 = *(const float4*)&Wv[o0]; pv1 = *(const float4*)&Wv[o1];
        }

        #pragma unroll
        for (int k4 = 0; k4 < BK; k4 += 4) {
            float4 a4[4];
            #pragma unroll
            for (int i = 0; i < 4; ++i)
                a4[i] = *(const float4*)&As[ty*4+i][k4];
            #pragma unroll
            for (int kk = 0; kk < 4; ++kk) {
                F4U2 bq, bk, bv;
                bq.f4 = *(const float4*)&Wqs[k4+kk][tx*4];
                bk.f4 = *(const float4*)&Wks[k4+kk][tx*4];
                bv.f4 = *(const float4*)&Wvs[k4+kk][tx*4];
                #pragma unroll
                for (int i = 0; i < 4; ++i) {
                    u64_t ad = pack_dup(COMP(a4[i], kk));
                    fma2(aq2[i][0], ad, bq.u2[0]);
                    fma2(aq2[i][1], ad, bq.u2[1]);
                    fma2(ak2[i][0], ad, bk.u2[0]);
                    fma2(ak2[i][1], ad, bk.u2[1]);
                    fma2(av2[i][0], ad, bv.u2[0]);
                    fma2(av2[i][1], ad, bv.u2[1]);
                }
            }
        }
        __syncthreads();
    }

    #pragma unroll
    for (int i = 0; i < 4; ++i) {
        size_t r = row0 + ty*4 + i;
        float v0, v1, v2, v3;
        unpack2(aq2[i][0], v0, v1); unpack2(aq2[i][1], v2, v3);
        *(float4*)&g_q[r*HS_ + tx*4] = make_float4(v0, v1, v2, v3);
        unpack2(ak2[i][0], v0, v1); unpack2(ak2[i][1], v2, v3);
        *(float4*)&g_k[r*HS_ + tx*4] = make_float4(v0, v1, v2, v3);
        unpack2(av2[i][0], v0, v1); unpack2(av2[i][1], v2, v3);
        *(float4*)&g_v[r*HS_ + tx*4] = make_float4(v0, v1, v2, v3);
    }
}

// ---------------------------------------------------------------------------
// Causal flash attention, HS=64. grid (T/32, B), 256 threads (8 warps),
// warp owns 4 query rows. Vectorized LDS (float4/u64), K/V/P reads shared
// across the warp's 4 rows, smem P tile instead of PV shuffles.
// Lane owns output cols (2*lane, 2*lane+1) as one f32x2 accumulator.
// ---------------------------------------------------------------------------
__global__ void __launch_bounds__(256)
flash_attn_kernel() {
    __shared__ float Qs[32][68];
    __shared__ float Ks[32][68];
    __shared__ float Vs[32][68];
    __shared__ float Ps[32][36];

    int b   = blockIdx.y;
    int qt  = blockIdx.x;
    int tid = threadIdx.x;
    int warp = tid >> 5, lane = tid & 31;
    const float scale = 0.125f;

    size_t base = (size_t)b * T_ * HS_;

    // Load Q tile (32x64) vectorized
    for (int i = tid; i < 512; i += 256) {
        int r = i >> 4, cg = i & 15;
        *(float4*)&Qs[r][cg*4] =
            *(const float4*)&g_q[base + (size_t)(qt*32 + r)*HS_ + cg*4];
    }

    const int r0 = (tid      ) >> 4, c0 = (tid      ) & 15;
    const int r1 = (tid + 256) >> 4, c1 = (tid + 256) & 15;

    float4 fk0, fk1, fv0, fv1;
    {
        size_t off0 = base + (size_t)r0*HS_ + c0*4;
        size_t off1 = base + (size_t)r1*HS_ + c1*4;
        fk0 = *(const float4*)&g_k[off0]; fk1 = *(const float4*)&g_k[off1];
        fv0 = *(const float4*)&g_v[off0]; fv1 = *(const float4*)&g_v[off1];
    }

    float m[4], l[4];
    u64_t o2[4];
    #pragma unroll
    for (int rr = 0; rr < 4; ++rr) { m[rr] = -3.0e38f; l[rr] = 0.f; o2[rr] = 0ull; }

    for (int j = 0; j <= qt; ++j) {
        __syncthreads();
        *(float4*)&Ks[r0][c0*4] = fk0; *(float4*)&Ks[r1][c1*4] = fk1;
        *(float4*)&Vs[r0][c0*4] = fv0; *(float4*)&Vs[r1][c1*4] = fv1;
        __syncthreads();

        if (j < qt) {
            size_t off0 = base + (size_t)((j+1)*32 + r0)*HS_ + c0*4;
            size_t off1 = base + (size_t)((j+1)*32 + r1)*HS_ + c1*4;
            fk0 = *(const float4*)&g_k[off0]; fk1 = *(const float4*)&g_k[off1];
            fv0 = *(const float4*)&g_v[off0]; fv1 = *(const float4*)&g_v[off1];
        }

        // ---- S for all 4 rows, K read once per chunk (shared across rows)
        u64_t s2a[4] = {0ull,0ull,0ull,0ull};
        u64_t s2b[4] = {0ull,0ull,0ull,0ull};
        #pragma unroll
        for (int kk = 0; kk < 16; ++kk) {
            F4U2 kv; kv.f4 = *(const float4*)&Ks[lane][kk*4];
            #pragma unroll
            for (int rr = 0; rr < 4; ++rr) {
                F4U2 qv; qv.f4 = *(const float4*)&Qs[warp*4+rr][kk*4];
                fma2(s2a[rr], qv.u2[0], kv.u2[0]);
                fma2(s2b[rr], qv.u2[1], kv.u2[1]);
            }
        }

        // ---- softmax per row (warp-wide over the 32 key columns)
        float alpha[4];
        #pragma unroll
        for (int rr = 0; rr < 4; ++rr) {
            int row  = warp*4 + rr;
            int grow = qt*32 + row;
            int gcol = j*32 + lane;
            float xa, ya, xb, yb;
            unpack2(s2a[rr], xa, ya); unpack2(s2b[rr], xb, yb);
            float s = (xa + xb) + (ya + yb);
            s *= scale;
            if (gcol > grow) s = -1.0e30f;

            float mt = s;
            #pragma unroll
            for (int off = 16; off; off >>= 1)
                mt = fmaxf(mt, __shfl_xor_sync(0xffffffffu, mt, off));
            float mnew = fmaxf(m[rr], mt);
            alpha[rr]  = __expf(m[rr] - mnew);
            float p    = __expf(s - mnew);

            float ps = p;
            #pragma unroll
            for (int off = 16; off; off >>= 1)
                ps += __shfl_xor_sync(0xffffffffu, ps, off);

            l[rr] = l[rr]*alpha[rr] + ps;
            m[rr] = mnew;
            Ps[row][lane] = p;
        }
        __syncwarp();

        #pragma unroll
        for (int rr = 0; rr < 4; ++rr) mul2(o2[rr], pack_dup(alpha[rr]));

        // ---- PV: V read once per column (shared across rows), P broadcast
        #pragma unroll
        for (int c4 = 0; c4 < 32; c4 += 4) {
            F4U2 p4[4];
            #pragma unroll
            for (int rr = 0; rr < 4; ++rr)
                p4[rr].f4 = *(const float4*)&Ps[warp*4+rr][c4];
            #pragma unroll
            for (int cc = 0; cc < 4; ++cc) {
                u64_t v2 = *(const u64_t*)&Vs[c4+cc][2*lane];
                #pragma unroll
                for (int rr = 0; rr < 4; ++rr) {
                    u64_t pd = pack_dup(COMP(p4[rr].f4, cc));
                    fma2(o2[rr], pd, v2);
                }
            }
        }
    }

    #pragma unroll
    for (int rr = 0; rr < 4; ++rr) {
        int grow = qt*32 + warp*4 + rr;
        float inv = 1.0f / l[rr];
        float lo, hi; unpack2(o2[rr], lo, hi);
        *(float2*)&g_ho[base + (size_t)grow*HS_ + 2*lane] =
            make_float2(lo*inv, hi*inv);
    }
}

// ---------------------------------------------------------------------------
// Output projection: out[M,1024] = g_ho[M,64] @ g_wp[64,1024] + bp
// FFMA2 + vectorized smem reads (A float4 per 4 k, B float4 per k).
// ---------------------------------------------------------------------------
__global__ void __launch_bounds__(256)
proj_kernel(const float* __restrict__ bp, float* __restrict__ out) {
    __shared__ float Hs[64][68];
    __shared__ float Ws[64][64];

    int tid = threadIdx.x;
    int tx = tid & 15, ty = tid >> 4;
    int row0 = blockIdx.x * 64, col0 = blockIdx.y * 64;

    for (int i = tid; i < 1024; i += 256) {
        int r = i >> 4, cg = i & 15;
        *(float4*)&Hs[r][cg*4] =
            *(const float4*)&g_ho[(size_t)(row0 + r)*HS_ + cg*4];
    }
    for (int i = tid; i < 1024; i += 256) {
        int r = i >> 4, cg = i & 15;
        *(float4*)&Ws[r][cg*4] = *(const float4*)&g_wp[(size_t)r*D_ + col0 + cg*4];
    }
    __syncthreads();

    u64_t acc2[4][2] = {};
    #pragma unroll
    for (int k4 = 0; k4 < 64; k4 += 4) {
        float4 a4[4];
        #pragma unroll
        for (int i = 0; i < 4; ++i)
            a4[i] = *(const float4*)&Hs[ty*4+i][k4];
        #pragma unroll
        for (int kk = 0; kk < 4; ++kk) {
            F4U2 bw; bw.f4 = *(const float4*)&Ws[k4+kk][tx*4];
            #pragma unroll
            for (int i = 0; i < 4; ++i) {
                u64_t ad = pack_dup(COMP(a4[i], kk));
                fma2(acc2[i][0], ad, bw.u2[0]);
                fma2(acc2[i][1], ad, bw.u2[1]);
            }
        }
    }

    float4 bias = *(const float4*)&bp[col0 + tx*4];
    #pragma unroll
    for (int i = 0; i < 4; ++i) {
        size_t r = row0 + ty*4 + i;
        float v0, v1, v2, v3;
        unpack2(acc2[i][0], v0, v1); unpack2(acc2[i][1], v2, v3);
        *(float4*)&out[r*D_ + col0 + tx*4] =
            make_float4(v0 + bias.x, v1 + bias.y, v2 + bias.z, v3 + bias.w);
    }
}

// ---------------------------------------------------------------------------
extern "C" void kernel_launch(void* const* d_in, const int* in_sizes, int n_in,
                              void* d_out, int out_size) {
    const float* x  = (const float*)d_in[0];
    const float* Wq = (const float*)d_in[1];
    const float* Wk = (const float*)d_in[2];
    const float* Wv = (const float*)d_in[3];
    const float* Wp = (const float*)d_in[4];
    const float* bp = (const float*)d_in[5];
    float* out = (float*)d_out;

    fold_wp_kernel<<<64, 1024>>>(Wp);
    qkv_gemm_kernel<<<M_/64, 256>>>(x, Wq, Wk, Wv);
    flash_attn_kernel<<<dim3(T_/32, B_), 256>>>();
    proj_kernel<<<dim3(M_/64, D_/64), 256>>>(bp, out);

    (void)in_sizes; (void)n_in; (void)out_size;
}

// round 14
// speedup vs baseline: 1.2280x; 1.2280x over previous
#include <cuda_runtime.h>
#include <cuda_bf16.h>

#define B_  16
#define T_  1024
#define D_  1024
#define HS_ 64
#define H_  16
#define M_  (B_*T_)   // 16384
#define NTOT 192      // q|k|v output columns

typedef unsigned long long u64_t;
typedef unsigned int u32_t;

// ---- packed f32x2 helpers (attention / proj) ----
__device__ __forceinline__ u64_t pack_dup(float v) {
    u64_t r; unsigned u = __float_as_uint(v);
    asm("mov.b64 %0, {%1, %1};" : "=l"(r) : "r"(u));
    return r;
}
__device__ __forceinline__ void fma2(u64_t &d, u64_t a, u64_t b) {
    asm("fma.rn.f32x2 %0, %1, %2, %0;" : "+l"(d) : "l"(a), "l"(b));
}
__device__ __forceinline__ void mul2(u64_t &d, u64_t a) {
    asm("mul.rn.f32x2 %0, %0, %1;" : "+l"(d) : "l"(a));
}
__device__ __forceinline__ void unpack2(u64_t v, float &lo, float &hi) {
    unsigned a, b;
    asm("mov.b64 {%0, %1}, %2;" : "=r"(a), "=r"(b) : "l"(v));
    lo = __uint_as_float(a); hi = __uint_as_float(b);
}
union F4U2 { float4 f4; u64_t u2[2]; };
#define COMP(v,kk) ((kk)==0?(v).x:(kk)==1?(v).y:(kk)==2?(v).z:(v).w)

// ---- mma helpers ----
__device__ __forceinline__ u32_t smem_u32(const void* p) {
    return (u32_t)__cvta_generic_to_shared(p);
}
__device__ __forceinline__ void ldsm_x4(u32_t& r0,u32_t& r1,u32_t& r2,u32_t& r3, u32_t a) {
    asm volatile("ldmatrix.sync.aligned.m8n8.x4.shared.b16 {%0,%1,%2,%3}, [%4];"
                 : "=r"(r0),"=r"(r1),"=r"(r2),"=r"(r3) : "r"(a));
}
__device__ __forceinline__ void ldsm_x2(u32_t& r0,u32_t& r1, u32_t a) {
    asm volatile("ldmatrix.sync.aligned.m8n8.x2.shared.b16 {%0,%1}, [%2];"
                 : "=r"(r0),"=r"(r1) : "r"(a));
}
__device__ __forceinline__ void mma_bf16(float* c, u32_t a0,u32_t a1,u32_t a2,u32_t a3,
                                         u32_t b0,u32_t b1) {
    asm volatile("mma.sync.aligned.m16n8k16.row.col.f32.bf16.bf16.f32 "
                 "{%0,%1,%2,%3}, {%4,%5,%6,%7}, {%8,%9}, {%0,%1,%2,%3};"
                 : "+f"(c[0]),"+f"(c[1]),"+f"(c[2]),"+f"(c[3])
                 : "r"(a0),"r"(a1),"r"(a2),"r"(a3),"r"(b0),"r"(b1));
}

// Scratch (device globals — no allocation allowed)
__device__ float g_q [M_*HS_];
__device__ float g_k [M_*HS_];
__device__ float g_v [M_*HS_];
__device__ float g_ho[M_*HS_];
__device__ float g_wp[HS_*D_];
__device__ __nv_bfloat16 g_wt_hi[NTOT][D_];   // W^T, bf16 hi part, [n][k]
__device__ __nv_bfloat16 g_wt_lo[NTOT][D_];   // W^T, bf16 lo part

// ---------------------------------------------------------------------------
// Fold Wp: Wp_eff[j][e] = sum_h Wp[h*HS+j][e]
// ---------------------------------------------------------------------------
__global__ void fold_wp_kernel(const float* __restrict__ Wp) {
    int idx = blockIdx.x * blockDim.x + threadIdx.x;
    int j = idx >> 10;
    int e = idx & 1023;
    float s = 0.f;
    #pragma unroll
    for (int h = 0; h < H_; ++h) s += Wp[(h*HS_ + j)*D_ + e];
    g_wp[idx] = s;
    (void)e; (void)j;
}

// ---------------------------------------------------------------------------
// Prep: transpose + bf16 hi/lo split of Wq|Wk|Wv into g_wt_hi/lo [192][1024]
// ---------------------------------------------------------------------------
__global__ void prep_wt_kernel(const float* __restrict__ Wq,
                               const float* __restrict__ Wk,
                               const float* __restrict__ Wv) {
    int idx = blockIdx.x * blockDim.x + threadIdx.x;   // 192*1024
    int n = idx >> 10, k = idx & 1023;
    const float* W = (n < 64) ? Wq : (n < 128) ? Wk : Wv;
    float w = W[(size_t)k*HS_ + (n & 63)];
    __nv_bfloat16 hi = __float2bfloat16(w);
    g_wt_hi[n][k] = hi;
    g_wt_lo[n][k] = __float2bfloat16(w - __bfloat162float(hi));
}

// ---------------------------------------------------------------------------
// QKV via tensor cores: {q,k,v}[M,64] = x[M,1024] @ W[1024,192]
// bf16 hi/lo split (3 products) -> rel err ~1e-5. BM=64, BK=32, all 192 cols.
// 8 warps = 2(M) x 4(N); warp = 32 rows x 48 cols; mma m16n8k16 + ldmatrix.
// ---------------------------------------------------------------------------
__global__ void __launch_bounds__(256)
qkv_mma_kernel(const float* __restrict__ x) {
    __shared__ __nv_bfloat16 xs_hi[64][40];     // [m][k], 80B row stride
    __shared__ __nv_bfloat16 xs_lo[64][40];
    __shared__ __nv_bfloat16 ws_hi[NTOT][40];   // [n][k]
    __shared__ __nv_bfloat16 ws_lo[NTOT][40];

    int tid  = threadIdx.x;
    int warp = tid >> 5, lane = tid & 31;
    int warp_m = warp >> 2;        // 0..1 -> rows 32*warp_m
    int warp_n = warp & 3;         // 0..3 -> cols 48*warp_n
    int row0 = blockIdx.x * 64;

    float acc[2][6][4];
    #pragma unroll
    for (int a = 0; a < 2; ++a)
        #pragma unroll
        for (int b = 0; b < 6; ++b)
            #pragma unroll
            for (int c = 0; c < 4; ++c) acc[a][b][c] = 0.f;

    // ldmatrix lane geometry
    int lane16 = lane & 15;
    int a_row16 = lane16;                 // row within 16-row tile
    int a_kadd  = (lane >> 4) * 16;       // +8 cols (bytes) for matrices 2,3
    int b_row8  = lane16 & 7;
    int b_kadd  = (lane16 >> 3) * 16;     // +8 cols (bytes) for matrix 1

    // staging coords
    int sr = tid >> 2, sc = (tid & 3) * 8;

    for (int kk = 0; kk < 32; ++kk) {
        __syncthreads();
        // stage x tile 64x32: fp32 -> (hi, lo) bf16
        {
            const float* xp = &x[(size_t)(row0 + sr)*D_ + kk*32 + sc];
            float4 f0 = *(const float4*)xp;
            float4 f1 = *(const float4*)(xp + 4);
            float f[8] = {f0.x,f0.y,f0.z,f0.w,f1.x,f1.y,f1.z,f1.w};
            #pragma unroll
            for (int i = 0; i < 8; i += 2) {
                __nv_bfloat16 h0 = __float2bfloat16(f[i]);
                __nv_bfloat16 h1 = __float2bfloat16(f[i+1]);
                __nv_bfloat162 hh; hh.x = h0; hh.y = h1;
                *(__nv_bfloat162*)&xs_hi[sr][sc+i] = hh;
                __nv_bfloat162 ll;
                ll.x = __float2bfloat16(f[i]   - __bfloat162float(h0));
                ll.y = __float2bfloat16(f[i+1] - __bfloat162float(h1));
                *(__nv_bfloat162*)&xs_lo[sr][sc+i] = ll;
            }
        }
        // stage W tiles 192x32 (hi, lo) from pre-split globals
        #pragma unroll
        for (int t3 = 0; t3 < 3; ++t3) {
            int q = tid + t3*256;          // 0..767
            int wrow = q >> 2, qi = q & 3;
            *(uint4*)&ws_hi[wrow][qi*8] = *(const uint4*)&g_wt_hi[wrow][kk*32 + qi*8];
            *(uint4*)&ws_lo[wrow][qi*8] = *(const uint4*)&g_wt_lo[wrow][kk*32 + qi*8];
        }
        __syncthreads();

        #pragma unroll
        for (int ks = 0; ks < 2; ++ks) {
            u32_t ah[2][4], al[2][4];
            #pragma unroll
            for (int mt = 0; mt < 2; ++mt) {
                int arow = warp_m*32 + mt*16 + a_row16;
                u32_t ha = smem_u32(&xs_hi[arow][0]) + ks*32 + a_kadd;
                u32_t la = smem_u32(&xs_lo[arow][0]) + ks*32 + a_kadd;
                ldsm_x4(ah[mt][0],ah[mt][1],ah[mt][2],ah[mt][3], ha);
                ldsm_x4(al[mt][0],al[mt][1],al[mt][2],al[mt][3], la);
            }
            #pragma unroll
            for (int nt = 0; nt < 6; ++nt) {
                int brow = warp_n*48 + nt*8 + b_row8;
                u32_t bh0,bh1,bl0,bl1;
                ldsm_x2(bh0,bh1, smem_u32(&ws_hi[brow][0]) + ks*32 + b_kadd);
                ldsm_x2(bl0,bl1, smem_u32(&ws_lo[brow][0]) + ks*32 + b_kadd);
                #pragma unroll
                for (int mt = 0; mt < 2; ++mt) {
                    mma_bf16(acc[mt][nt], ah[mt][0],ah[mt][1],ah[mt][2],ah[mt][3], bh0,bh1);
                    mma_bf16(acc[mt][nt], ah[mt][0],ah[mt][1],ah[mt][2],ah[mt][3], bl0,bl1);
                    mma_bf16(acc[mt][nt], al[mt][0],al[mt][1],al[mt][2],al[mt][3], bh0,bh1);
                }
            }
        }
    }

    // epilogue: c0,c1 = (row g, col 2t..2t+1); c2,c3 = (row g+8, same cols)
    int g = lane >> 2, t = lane & 3;
    #pragma unroll
    for (int mt = 0; mt < 2; ++mt) {
        int r_lo = row0 + warp_m*32 + mt*16 + g;
        #pragma unroll
        for (int nt = 0; nt < 6; ++nt) {
            int col_g = warp_n*48 + nt*8 + 2*t;
            float* outp = (col_g < 64) ? g_q : (col_g < 128) ? g_k : g_v;
            int cc = col_g & 63;
            *(float2*)&outp[(size_t)r_lo*HS_ + cc] =
                make_float2(acc[mt][nt][0], acc[mt][nt][1]);
            *(float2*)&outp[(size_t)(r_lo+8)*HS_ + cc] =
                make_float2(acc[mt][nt][2], acc[mt][nt][3]);
        }
    }
}

// ---------------------------------------------------------------------------
// Causal flash attention (unchanged from R13 passing version)
// ---------------------------------------------------------------------------
__global__ void __launch_bounds__(256)
flash_attn_kernel() {
    __shared__ float Qs[32][68];
    __shared__ float Ks[32][68];
    __shared__ float Vs[32][68];
    __shared__ float Ps[32][36];

    int b   = blockIdx.y;
    int qt  = blockIdx.x;
    int tid = threadIdx.x;
    int warp = tid >> 5, lane = tid & 31;
    const float scale = 0.125f;

    size_t base = (size_t)b * T_ * HS_;

    for (int i = tid; i < 512; i += 256) {
        int r = i >> 4, cg = i & 15;
        *(float4*)&Qs[r][cg*4] =
            *(const float4*)&g_q[base + (size_t)(qt*32 + r)*HS_ + cg*4];
    }

    const int r0 = (tid      ) >> 4, c0 = (tid      ) & 15;
    const int r1 = (tid + 256) >> 4, c1 = (tid + 256) & 15;

    float4 fk0, fk1, fv0, fv1;
    {
        size_t off0 = base + (size_t)r0*HS_ + c0*4;
        size_t off1 = base + (size_t)r1*HS_ + c1*4;
        fk0 = *(const float4*)&g_k[off0]; fk1 = *(const float4*)&g_k[off1];
        fv0 = *(const float4*)&g_v[off0]; fv1 = *(const float4*)&g_v[off1];
    }

    float m[4], l[4];
    u64_t o2[4];
    #pragma unroll
    for (int rr = 0; rr < 4; ++rr) { m[rr] = -3.0e38f; l[rr] = 0.f; o2[rr] = 0ull; }

    for (int j = 0; j <= qt; ++j) {
        __syncthreads();
        *(float4*)&Ks[r0][c0*4] = fk0; *(float4*)&Ks[r1][c1*4] = fk1;
        *(float4*)&Vs[r0][c0*4] = fv0; *(float4*)&Vs[r1][c1*4] = fv1;
        __syncthreads();

        if (j < qt) {
            size_t off0 = base + (size_t)((j+1)*32 + r0)*HS_ + c0*4;
            size_t off1 = base + (size_t)((j+1)*32 + r1)*HS_ + c1*4;
            fk0 = *(const float4*)&g_k[off0]; fk1 = *(const float4*)&g_k[off1];
            fv0 = *(const float4*)&g_v[off0]; fv1 = *(const float4*)&g_v[off1];
        }

        u64_t s2a[4] = {0ull,0ull,0ull,0ull};
        u64_t s2b[4] = {0ull,0ull,0ull,0ull};
        #pragma unroll
        for (int kk = 0; kk < 16; ++kk) {
            F4U2 kv; kv.f4 = *(const float4*)&Ks[lane][kk*4];
            #pragma unroll
            for (int rr = 0; rr < 4; ++rr) {
                F4U2 qv; qv.f4 = *(const float4*)&Qs[warp*4+rr][kk*4];
                fma2(s2a[rr], qv.u2[0], kv.u2[0]);
                fma2(s2b[rr], qv.u2[1], kv.u2[1]);
            }
        }

        float alpha[4];
        #pragma unroll
        for (int rr = 0; rr < 4; ++rr) {
            int row  = warp*4 + rr;
            int grow = qt*32 + row;
            int gcol = j*32 + lane;
            float xa, ya, xb, yb;
            unpack2(s2a[rr], xa, ya); unpack2(s2b[rr], xb, yb);
            float s = (xa + xb) + (ya + yb);
            s *= scale;
            if (gcol > grow) s = -1.0e30f;

            float mt = s;
            #pragma unroll
            for (int off = 16; off; off >>= 1)
                mt = fmaxf(mt, __shfl_xor_sync(0xffffffffu, mt, off));
            float mnew = fmaxf(m[rr], mt);
            alpha[rr]  = __expf(m[rr] - mnew);
            float p    = __expf(s - mnew);

            float ps = p;
            #pragma unroll
            for (int off = 16; off; off >>= 1)
                ps += __shfl_xor_sync(0xffffffffu, ps, off);

            l[rr] = l[rr]*alpha[rr] + ps;
            m[rr] = mnew;
            Ps[row][lane] = p;
        }
        __syncwarp();

        #pragma unroll
        for (int rr = 0; rr < 4; ++rr) mul2(o2[rr], pack_dup(alpha[rr]));

        #pragma unroll
        for (int c4 = 0; c4 < 32; c4 += 4) {
            F4U2 p4[4];
            #pragma unroll
            for (int rr = 0; rr < 4; ++rr)
                p4[rr].f4 = *(const float4*)&Ps[warp*4+rr][c4];
            #pragma unroll
            for (int cc = 0; cc < 4; ++cc) {
                u64_t v2 = *(const u64_t*)&Vs[c4+cc][2*lane];
                #pragma unroll
                for (int rr = 0; rr < 4; ++rr) {
                    u64_t pd = pack_dup(COMP(p4[rr].f4, cc));
                    fma2(o2[rr], pd, v2);
                }
            }
        }
    }

    #pragma unroll
    for (int rr = 0; rr < 4; ++rr) {
        int grow = qt*32 + warp*4 + rr;
        float inv = 1.0f / l[rr];
        float lo, hi; unpack2(o2[rr], lo, hi);
        *(float2*)&g_ho[base + (size_t)grow*HS_ + 2*lane] =
            make_float2(lo*inv, hi*inv);
    }
}

// ---------------------------------------------------------------------------
// Output projection (unchanged from R13 passing version)
// ---------------------------------------------------------------------------
__global__ void __launch_bounds__(256)
proj_kernel(const float* __restrict__ bp, float* __restrict__ out) {
    __shared__ float Hs[64][68];
    __shared__ float Ws[64][64];

    int tid = threadIdx.x;
    int tx = tid & 15, ty = tid >> 4;
    int row0 = blockIdx.x * 64, col0 = blockIdx.y * 64;

    for (int i = tid; i < 1024; i += 256) {
        int r = i >> 4, cg = i & 15;
        *(float4*)&Hs[r][cg*4] =
            *(const float4*)&g_ho[(size_t)(row0 + r)*HS_ + cg*4];
    }
    for (int i = tid; i < 1024; i += 256) {
        int r = i >> 4, cg = i & 15;
        *(float4*)&Ws[r][cg*4] = *(const float4*)&g_wp[(size_t)r*D_ + col0 + cg*4];
    }
    __syncthreads();

    u64_t acc2[4][2] = {};
    #pragma unroll
    for (int k4 = 0; k4 < 64; k4 += 4) {
        float4 a4[4];
        #pragma unroll
        for (int i = 0; i < 4; ++i)
            a4[i] = *(const float4*)&Hs[ty*4+i][k4];
        #pragma unroll
        for (int kk = 0; kk < 4; ++kk) {
            F4U2 bw; bw.f4 = *(const float4*)&Ws[k4+kk][tx*4];
            #pragma unroll
            for (int i = 0; i < 4; ++i) {
                u64_t ad = pack_dup(COMP(a4[i], kk));
                fma2(acc2[i][0], ad, bw.u2[0]);
                fma2(acc2[i][1], ad, bw.u2[1]);
            }
        }
    }

    float4 bias = *(const float4*)&bp[col0 + tx*4];
    #pragma unroll
    for (int i = 0; i < 4; ++i) {
        size_t r = row0 + ty*4 + i;
        float v0, v1, v2, v3;
        unpack2(acc2[i][0], v0, v1); unpack2(acc2[i][1], v2, v3);
        *(float4*)&out[r*D_ + col0 + tx*4] =
            make_float4(v0 + bias.x, v1 + bias.y, v2 + bias.z, v3 + bias.w);
    }
}

// ---------------------------------------------------------------------------
extern "C" void kernel_launch(void* const* d_in, const int* in_sizes, int n_in,
                              void* d_out, int out_size) {
    const float* x  = (const float*)d_in[0];
    const float* Wq = (const float*)d_in[1];
    const float* Wk = (const float*)d_in[2];
    const float* Wv = (const float*)d_in[3];
    const float* Wp = (const float*)d_in[4];
    const float* bp = (const float*)d_in[5];
    float* out = (float*)d_out;

    fold_wp_kernel<<<64, 1024>>>(Wp);
    prep_wt_kernel<<<NTOT*D_/256, 256>>>(Wq, Wk, Wv);
    qkv_mma_kernel<<<M_/64, 256>>>(x);
    flash_attn_kernel<<<dim3(T_/32, B_), 256>>>();
    proj_kernel<<<dim3(M_/64, D_/64), 256>>>(bp, out);

    (void)in_sizes; (void)n_in; (void)out_size;
}

// round 16
// speedup vs baseline: 1.4255x; 1.1609x over previous
#include <cuda_runtime.h>
#include <cuda_bf16.h>

#define B_  16
#define T_  1024
#define D_  1024
#define HS_ 64
#define H_  16
#define M_  (B_*T_)   // 16384
#define NTOT 192      // q|k|v output columns

typedef unsigned long long u64_t;
typedef unsigned int u32_t;

// ---- packed f32x2 helpers (proj) ----
__device__ __forceinline__ u64_t pack_dup(float v) {
    u64_t r; unsigned u = __float_as_uint(v);
    asm("mov.b64 %0, {%1, %1};" : "=l"(r) : "r"(u));
    return r;
}
__device__ __forceinline__ void fma2(u64_t &d, u64_t a, u64_t b) {
    asm("fma.rn.f32x2 %0, %1, %2, %0;" : "+l"(d) : "l"(a), "l"(b));
}
__device__ __forceinline__ void unpack2(u64_t v, float &lo, float &hi) {
    unsigned a, b;
    asm("mov.b64 {%0, %1}, %2;" : "=r"(a), "=r"(b) : "l"(v));
    lo = __uint_as_float(a); hi = __uint_as_float(b);
}
union F4U2 { float4 f4; u64_t u2[2]; };
#define COMP(v,kk) ((kk)==0?(v).x:(kk)==1?(v).y:(kk)==2?(v).z:(v).w)

// ---- mma helpers (validated R14) ----
__device__ __forceinline__ u32_t smem_u32(const void* p) {
    return (u32_t)__cvta_generic_to_shared(p);
}
__device__ __forceinline__ void ldsm_x4(u32_t& r0,u32_t& r1,u32_t& r2,u32_t& r3, u32_t a) {
    asm volatile("ldmatrix.sync.aligned.m8n8.x4.shared.b16 {%0,%1,%2,%3}, [%4];"
                 : "=r"(r0),"=r"(r1),"=r"(r2),"=r"(r3) : "r"(a));
}
__device__ __forceinline__ void ldsm_x2(u32_t& r0,u32_t& r1, u32_t a) {
    asm volatile("ldmatrix.sync.aligned.m8n8.x2.shared.b16 {%0,%1}, [%2];"
                 : "=r"(r0),"=r"(r1) : "r"(a));
}
__device__ __forceinline__ void mma_bf16(float* c, u32_t a0,u32_t a1,u32_t a2,u32_t a3,
                                         u32_t b0,u32_t b1) {
    asm volatile("mma.sync.aligned.m16n8k16.row.col.f32.bf16.bf16.f32 "
                 "{%0,%1,%2,%3}, {%4,%5,%6,%7}, {%8,%9}, {%0,%1,%2,%3};"
                 : "+f"(c[0]),"+f"(c[1]),"+f"(c[2]),"+f"(c[3])
                 : "r"(a0),"r"(a1),"r"(a2),"r"(a3),"r"(b0),"r"(b1));
}
// pack two fp32 into bf16x2 (lo = first), plus residual pack
__device__ __forceinline__ u32_t pack_bf16x2(float c0, float c1) {
    __nv_bfloat162 hh; hh.x = __float2bfloat16(c0); hh.y = __float2bfloat16(c1);
    return *(u32_t*)&hh;
}
__device__ __forceinline__ u32_t pack_bf16x2_res(float c0, float c1, u32_t hi) {
    __nv_bfloat162 hh = *(__nv_bfloat162*)&hi;
    __nv_bfloat162 ll;
    ll.x = __float2bfloat16(c0 - __bfloat162float(hh.x));
    ll.y = __float2bfloat16(c1 - __bfloat162float(hh.y));
    return *(u32_t*)&ll;
}

// Scratch (device globals — no allocation allowed)
__device__ float g_q [M_*HS_];
__device__ float g_k [M_*HS_];
__device__ float g_v [M_*HS_];
__device__ float g_ho[M_*HS_];
__device__ float g_wp[HS_*D_];
__device__ __nv_bfloat16 g_wt_hi[NTOT][D_];
__device__ __nv_bfloat16 g_wt_lo[NTOT][D_];

// ---------------------------------------------------------------------------
// Fold Wp
// ---------------------------------------------------------------------------
__global__ void fold_wp_kernel(const float* __restrict__ Wp) {
    int idx = blockIdx.x * blockDim.x + threadIdx.x;
    int j = idx >> 10;
    int e = idx & 1023;
    float s = 0.f;
    #pragma unroll
    for (int h = 0; h < H_; ++h) s += Wp[(h*HS_ + j)*D_ + e];
    g_wp[idx] = s;
    (void)e; (void)j;
}

// ---------------------------------------------------------------------------
// Prep: transpose + bf16 hi/lo split of Wq|Wk|Wv
// ---------------------------------------------------------------------------
__global__ void prep_wt_kernel(const float* __restrict__ Wq,
                               const float* __restrict__ Wk,
                               const float* __restrict__ Wv) {
    int idx = blockIdx.x * blockDim.x + threadIdx.x;
    int n = idx >> 10, k = idx & 1023;
    const float* W = (n < 64) ? Wq : (n < 128) ? Wk : Wv;
    float w = W[(size_t)k*HS_ + (n & 63)];
    __nv_bfloat16 hi = __float2bfloat16(w);
    g_wt_hi[n][k] = hi;
    g_wt_lo[n][k] = __float2bfloat16(w - __bfloat162float(hi));
}

// ---------------------------------------------------------------------------
// QKV via tensor cores (unchanged from R14 passing version)
// ---------------------------------------------------------------------------
__global__ void __launch_bounds__(256)
qkv_mma_kernel(const float* __restrict__ x) {
    __shared__ __nv_bfloat16 xs_hi[64][40];
    __shared__ __nv_bfloat16 xs_lo[64][40];
    __shared__ __nv_bfloat16 ws_hi[NTOT][40];
    __shared__ __nv_bfloat16 ws_lo[NTOT][40];

    int tid  = threadIdx.x;
    int warp = tid >> 5, lane = tid & 31;
    int warp_m = warp >> 2;
    int warp_n = warp & 3;
    int row0 = blockIdx.x * 64;

    float acc[2][6][4];
    #pragma unroll
    for (int a = 0; a < 2; ++a)
        #pragma unroll
        for (int b = 0; b < 6; ++b)
            #pragma unroll
            for (int c = 0; c < 4; ++c) acc[a][b][c] = 0.f;

    int lane16 = lane & 15;
    int a_row16 = lane16;
    int a_kadd  = (lane >> 4) * 16;
    int b_row8  = lane16 & 7;
    int b_kadd  = (lane16 >> 3) * 16;

    int sr = tid >> 2, sc = (tid & 3) * 8;

    for (int kk = 0; kk < 32; ++kk) {
        __syncthreads();
        {
            const float* xp = &x[(size_t)(row0 + sr)*D_ + kk*32 + sc];
            float4 f0 = *(const float4*)xp;
            float4 f1 = *(const float4*)(xp + 4);
            float f[8] = {f0.x,f0.y,f0.z,f0.w,f1.x,f1.y,f1.z,f1.w};
            #pragma unroll
            for (int i = 0; i < 8; i += 2) {
                __nv_bfloat16 h0 = __float2bfloat16(f[i]);
                __nv_bfloat16 h1 = __float2bfloat16(f[i+1]);
                __nv_bfloat162 hh; hh.x = h0; hh.y = h1;
                *(__nv_bfloat162*)&xs_hi[sr][sc+i] = hh;
                __nv_bfloat162 ll;
                ll.x = __float2bfloat16(f[i]   - __bfloat162float(h0));
                ll.y = __float2bfloat16(f[i+1] - __bfloat162float(h1));
                *(__nv_bfloat162*)&xs_lo[sr][sc+i] = ll;
            }
        }
        #pragma unroll
        for (int t3 = 0; t3 < 3; ++t3) {
            int q = tid + t3*256;
            int wrow = q >> 2, qi = q & 3;
            *(uint4*)&ws_hi[wrow][qi*8] = *(const uint4*)&g_wt_hi[wrow][kk*32 + qi*8];
            *(uint4*)&ws_lo[wrow][qi*8] = *(const uint4*)&g_wt_lo[wrow][kk*32 + qi*8];
        }
        __syncthreads();

        #pragma unroll
        for (int ks = 0; ks < 2; ++ks) {
            u32_t ah[2][4], al[2][4];
            #pragma unroll
            for (int mt = 0; mt < 2; ++mt) {
                int arow = warp_m*32 + mt*16 + a_row16;
                u32_t ha = smem_u32(&xs_hi[arow][0]) + ks*32 + a_kadd;
                u32_t la = smem_u32(&xs_lo[arow][0]) + ks*32 + a_kadd;
                ldsm_x4(ah[mt][0],ah[mt][1],ah[mt][2],ah[mt][3], ha);
                ldsm_x4(al[mt][0],al[mt][1],al[mt][2],al[mt][3], la);
            }
            #pragma unroll
            for (int nt = 0; nt < 6; ++nt) {
                int brow = warp_n*48 + nt*8 + b_row8;
                u32_t bh0,bh1,bl0,bl1;
                ldsm_x2(bh0,bh1, smem_u32(&ws_hi[brow][0]) + ks*32 + b_kadd);
                ldsm_x2(bl0,bl1, smem_u32(&ws_lo[brow][0]) + ks*32 + b_kadd);
                #pragma unroll
                for (int mt = 0; mt < 2; ++mt) {
                    mma_bf16(acc[mt][nt], ah[mt][0],ah[mt][1],ah[mt][2],ah[mt][3], bh0,bh1);
                    mma_bf16(acc[mt][nt], ah[mt][0],ah[mt][1],ah[mt][2],ah[mt][3], bl0,bl1);
                    mma_bf16(acc[mt][nt], al[mt][0],al[mt][1],al[mt][2],al[mt][3], bh0,bh1);
                }
            }
        }
    }

    int g = lane >> 2, t = lane & 3;
    #pragma unroll
    for (int mt = 0; mt < 2; ++mt) {
        int r_lo = row0 + warp_m*32 + mt*16 + g;
        #pragma unroll
        for (int nt = 0; nt < 6; ++nt) {
            int col_g = warp_n*48 + nt*8 + 2*t;
            float* outp = (col_g < 64) ? g_q : (col_g < 128) ? g_k : g_v;
            int cc = col_g & 63;
            *(float2*)&outp[(size_t)r_lo*HS_ + cc] =
                make_float2(acc[mt][nt][0], acc[mt][nt][1]);
            *(float2*)&outp[(size_t)(r_lo+8)*HS_ + cc] =
                make_float2(acc[mt][nt][2], acc[mt][nt][3]);
        }
    }
}

// ---------------------------------------------------------------------------
// Tensor-core causal flash attention.
// Block: 64 Q rows, 128 threads (4 warps); warp = m16 x full width.
// KV tile 32. S = QK^T bf16 hi/lo (3 mma); softmax fp32 (quad shuffles);
// PV: P->bf16 hi/lo in registers, V staged transposed [hs][kv] (3 mma).
// ---------------------------------------------------------------------------
__global__ void __launch_bounds__(128)
flash_attn_kernel() {
    __shared__ __nv_bfloat16 Qh[64][72], Ql[64][72];   // [m][k] 144B rows
    __shared__ __nv_bfloat16 Kh[32][72], Kl[32][72];   // [n(kv)][k(hs)]
    __shared__ __nv_bfloat16 Vh[64][40], Vl[64][40];   // transposed: [n(hs)][k(kv)]

    int b = blockIdx.y, qt = blockIdx.x;
    int tid = threadIdx.x, warp = tid >> 5, lane = tid & 31;
    int lane16 = lane & 15;
    int a_row  = lane16, a_kadd = (lane >> 4) * 16;
    int b_row8 = lane16 & 7, b_kadd = (lane16 >> 3) * 16;
    int g = lane >> 2, t = lane & 3;
    size_t base = (size_t)b * T_ * HS_;
    const float scale = 0.125f;

    // ---- stage Q tile (64x64) as bf16 hi/lo
    #pragma unroll
    for (int tch = 0; tch < 4; ++tch) {
        int q = tid + tch*128;            // 0..511
        int r = q >> 3, c8 = (q & 7) * 8;
        const float* qp = &g_q[base + (size_t)(qt*64 + r)*HS_ + c8];
        float4 f0 = *(const float4*)qp, f1 = *(const float4*)(qp+4);
        float f[8] = {f0.x,f0.y,f0.z,f0.w,f1.x,f1.y,f1.z,f1.w};
        #pragma unroll
        for (int i = 0; i < 8; ++i) {
            __nv_bfloat16 h = __float2bfloat16(f[i]);
            Qh[r][c8+i] = h;
            Ql[r][c8+i] = __float2bfloat16(f[i] - __bfloat162float(h));
        }
    }
    __syncthreads();

    // ---- per-warp Q fragments (loop-invariant)
    u32_t qh[4][4], ql[4][4];
    #pragma unroll
    for (int kt = 0; kt < 4; ++kt) {
        u32_t ha = smem_u32(&Qh[warp*16 + a_row][0]) + kt*32 + a_kadd;
        u32_t la = smem_u32(&Ql[warp*16 + a_row][0]) + kt*32 + a_kadd;
        ldsm_x4(qh[kt][0],qh[kt][1],qh[kt][2],qh[kt][3], ha);
        ldsm_x4(ql[kt][0],ql[kt][1],ql[kt][2],ql[kt][3], la);
    }

    float m2[2] = {-3.0e38f, -3.0e38f};
    float l2[2] = {0.f, 0.f};
    float oc[8][4];
    #pragma unroll
    for (int n8 = 0; n8 < 8; ++n8)
        #pragma unroll
        for (int c = 0; c < 4; ++c) oc[n8][c] = 0.f;

    int R0 = qt*64 + warp*16;
    int jmax = 2*qt + 1;

    for (int j = 0; j <= jmax; ++j) {
        __syncthreads();
        // ---- stage K (32x64) and V transposed (hi/lo)
        #pragma unroll
        for (int tch = 0; tch < 2; ++tch) {
            int q = tid + tch*128;        // 0..255
            int r = q >> 3, c8 = (q & 7) * 8;
            size_t off = base + (size_t)(j*32 + r)*HS_ + c8;
            {
                const float* kp = &g_k[off];
                float4 f0 = *(const float4*)kp, f1 = *(const float4*)(kp+4);
                float f[8] = {f0.x,f0.y,f0.z,f0.w,f1.x,f1.y,f1.z,f1.w};
                #pragma unroll
                for (int i = 0; i < 8; ++i) {
                    __nv_bfloat16 h = __float2bfloat16(f[i]);
                    Kh[r][c8+i] = h;
                    Kl[r][c8+i] = __float2bfloat16(f[i] - __bfloat162float(h));
                }
            }
            {
                const float* vp = &g_v[off];
                float4 f0 = *(const float4*)vp, f1 = *(const float4*)(vp+4);
                float f[8] = {f0.x,f0.y,f0.z,f0.w,f1.x,f1.y,f1.z,f1.w};
                #pragma unroll
                for (int i = 0; i < 8; ++i) {
                    __nv_bfloat16 h = __float2bfloat16(f[i]);
                    Vh[c8+i][r] = h;                      // transpose
                    Vl[c8+i][r] = __float2bfloat16(f[i] - __bfloat162float(h));
                }
            }
        }
        __syncthreads();

        if (32*j <= R0 + 15) {
            // ---- S = Q K^T (m16 x n32, k64), 3 bf16 products
            float sC[4][4];
            #pragma unroll
            for (int nt = 0; nt < 4; ++nt)
                #pragma unroll
                for (int c = 0; c < 4; ++c) sC[nt][c] = 0.f;

            #pragma unroll
            for (int kt = 0; kt < 4; ++kt)
                #pragma unroll
                for (int nt = 0; nt < 4; ++nt) {
                    u32_t bh0,bh1,bl0,bl1;
                    ldsm_x2(bh0,bh1, smem_u32(&Kh[nt*8 + b_row8][0]) + kt*32 + b_kadd);
                    ldsm_x2(bl0,bl1, smem_u32(&Kl[nt*8 + b_row8][0]) + kt*32 + b_kadd);
                    mma_bf16(sC[nt], qh[kt][0],qh[kt][1],qh[kt][2],qh[kt][3], bh0,bh1);
                    mma_bf16(sC[nt], qh[kt][0],qh[kt][1],qh[kt][2],qh[kt][3], bl0,bl1);
                    mma_bf16(sC[nt], ql[kt][0],ql[kt][1],ql[kt][2],ql[kt][3], bh0,bh1);
                }

            // ---- scale + causal mask; rows rg = R0+g (c0,c1), rg8 = R0+g+8 (c2,c3)
            int rg  = R0 + g;
            int rg8 = rg + 8;
            float mx0 = -3.0e38f, mx1 = -3.0e38f;
            #pragma unroll
            for (int nt = 0; nt < 4; ++nt) {
                int colb = j*32 + nt*8 + 2*t;
                float s0 = sC[nt][0]*scale; if (colb     > rg ) s0 = -1.0e30f;
                float s1 = sC[nt][1]*scale; if (colb + 1 > rg ) s1 = -1.0e30f;
                float s2 = sC[nt][2]*scale; if (colb     > rg8) s2 = -1.0e30f;
                float s3 = sC[nt][3]*scale; if (colb + 1 > rg8) s3 = -1.0e30f;
                sC[nt][0] = s0; sC[nt][1] = s1; sC[nt][2] = s2; sC[nt][3] = s3;
                mx0 = fmaxf(mx0, fmaxf(s0, s1));
                mx1 = fmaxf(mx1, fmaxf(s2, s3));
            }
            // quad reduce (over t = lane bits 0..1)
            #pragma unroll
            for (int d = 1; d <= 2; d <<= 1) {
                mx0 = fmaxf(mx0, __shfl_xor_sync(0xffffffffu, mx0, d));
                mx1 = fmaxf(mx1, __shfl_xor_sync(0xffffffffu, mx1, d));
            }
            float mn0 = fmaxf(m2[0], mx0), mn1 = fmaxf(m2[1], mx1);
            float al0 = __expf(m2[0] - mn0), al1 = __expf(m2[1] - mn1);
            float sum0 = 0.f, sum1 = 0.f;
            #pragma unroll
            for (int nt = 0; nt < 4; ++nt) {
                float p0 = __expf(sC[nt][0] - mn0);
                float p1 = __expf(sC[nt][1] - mn0);
                float p2 = __expf(sC[nt][2] - mn1);
                float p3 = __expf(sC[nt][3] - mn1);
                sC[nt][0] = p0; sC[nt][1] = p1; sC[nt][2] = p2; sC[nt][3] = p3;
                sum0 += p0 + p1; sum1 += p2 + p3;
            }
            #pragma unroll
            for (int d = 1; d <= 2; d <<= 1) {
                sum0 += __shfl_xor_sync(0xffffffffu, sum0, d);
                sum1 += __shfl_xor_sync(0xffffffffu, sum1, d);
            }
            l2[0] = l2[0]*al0 + sum0; m2[0] = mn0;
            l2[1] = l2[1]*al1 + sum1; m2[1] = mn1;

            // rescale O
            #pragma unroll
            for (int n8 = 0; n8 < 8; ++n8) {
                oc[n8][0] *= al0; oc[n8][1] *= al0;
                oc[n8][2] *= al1; oc[n8][3] *= al1;
            }

            // ---- P -> bf16 hi/lo A-fragments (2 k16 tiles over kv32)
            u32_t pah[2][4], pal[2][4];
            #pragma unroll
            for (int i = 0; i < 2; ++i) {
                pah[i][0] = pack_bf16x2(sC[2*i][0],   sC[2*i][1]);
                pah[i][1] = pack_bf16x2(sC[2*i][2],   sC[2*i][3]);
                pah[i][2] = pack_bf16x2(sC[2*i+1][0], sC[2*i+1][1]);
                pah[i][3] = pack_bf16x2(sC[2*i+1][2], sC[2*i+1][3]);
                pal[i][0] = pack_bf16x2_res(sC[2*i][0],   sC[2*i][1],   pah[i][0]);
                pal[i][1] = pack_bf16x2_res(sC[2*i][2],   sC[2*i][3],   pah[i][1]);
                pal[i][2] = pack_bf16x2_res(sC[2*i+1][0], sC[2*i+1][1], pah[i][2]);
                pal[i][3] = pack_bf16x2_res(sC[2*i+1][2], sC[2*i+1][3], pah[i][3]);
            }

            // ---- O += P V  (m16 x n64, k32), 3 products
            #pragma unroll
            for (int i = 0; i < 2; ++i)
                #pragma unroll
                for (int n8 = 0; n8 < 8; ++n8) {
                    u32_t vh0,vh1,vl0,vl1;
                    ldsm_x2(vh0,vh1, smem_u32(&Vh[n8*8 + b_row8][0]) + i*32 + b_kadd);
                    ldsm_x2(vl0,vl1, smem_u32(&Vl[n8*8 + b_row8][0]) + i*32 + b_kadd);
                    mma_bf16(oc[n8], pah[i][0],pah[i][1],pah[i][2],pah[i][3], vh0,vh1);
                    mma_bf16(oc[n8], pah[i][0],pah[i][1],pah[i][2],pah[i][3], vl0,vl1);
                    mma_bf16(oc[n8], pal[i][0],pal[i][1],pal[i][2],pal[i][3], vh0,vh1);
                }
        }
    }

    // ---- epilogue: normalize and store
    float inv0 = 1.0f / l2[0], inv1 = 1.0f / l2[1];
    int rg  = R0 + g;
    #pragma unroll
    for (int n8 = 0; n8 < 8; ++n8) {
        int col = n8*8 + 2*t;
        *(float2*)&g_ho[base + (size_t)rg*HS_ + col] =
            make_float2(oc[n8][0]*inv0, oc[n8][1]*inv0);
        *(float2*)&g_ho[base + (size_t)(rg+8)*HS_ + col] =
            make_float2(oc[n8][2]*inv1, oc[n8][3]*inv1);
    }
}

// ---------------------------------------------------------------------------
// Output projection (unchanged from R13/R14 passing version)
// ---------------------------------------------------------------------------
__global__ void __launch_bounds__(256)
proj_kernel(const float* __restrict__ bp, float* __restrict__ out) {
    __shared__ float Hs[64][68];
    __shared__ float Ws[64][64];

    int tid = threadIdx.x;
    int tx = tid & 15, ty = tid >> 4;
    int row0 = blockIdx.x * 64, col0 = blockIdx.y * 64;

    for (int i = tid; i < 1024; i += 256) {
        int r = i >> 4, cg = i & 15;
        *(float4*)&Hs[r][cg*4] =
            *(const float4*)&g_ho[(size_t)(row0 + r)*HS_ + cg*4];
    }
    for (int i = tid; i < 1024; i += 256) {
        int r = i >> 4, cg = i & 15;
        *(float4*)&Ws[r][cg*4] = *(const float4*)&g_wp[(size_t)r*D_ + col0 + cg*4];
    }
    __syncthreads();

    u64_t acc2[4][2] = {};
    #pragma unroll
    for (int k4 = 0; k4 < 64; k4 += 4) {
        float4 a4[4];
        #pragma unroll
        for (int i = 0; i < 4; ++i)
            a4[i] = *(const float4*)&Hs[ty*4+i][k4];
        #pragma unroll
        for (int kk = 0; kk < 4; ++kk) {
            F4U2 bw; bw.f4 = *(const float4*)&Ws[k4+kk][tx*4];
            #pragma unroll
            for (int i = 0; i < 4; ++i) {
                u64_t ad = pack_dup(COMP(a4[i], kk));
                fma2(acc2[i][0], ad, bw.u2[0]);
                fma2(acc2[i][1], ad, bw.u2[1]);
            }
        }
    }

    float4 bias = *(const float4*)&bp[col0 + tx*4];
    #pragma unroll
    for (int i = 0; i < 4; ++i) {
        size_t r = row0 + ty*4 + i;
        float v0, v1, v2, v3;
        unpack2(acc2[i][0], v0, v1); unpack2(acc2[i][1], v2, v3);
        *(float4*)&out[r*D_ + col0 + tx*4] =
            make_float4(v0 + bias.x, v1 + bias.y, v2 + bias.z, v3 + bias.w);
    }
}

// ---------------------------------------------------------------------------
extern "C" void kernel_launch(void* const* d_in, const int* in_sizes, int n_in,
                              void* d_out, int out_size) {
    const float* x  = (const float*)d_in[0];
    const float* Wq = (const float*)d_in[1];
    const float* Wk = (const float*)d_in[2];
    const float* Wv = (const float*)d_in[3];
    const float* Wp = (const float*)d_in[4];
    const float* bp = (const float*)d_in[5];
    float* out = (float*)d_out;

    fold_wp_kernel<<<64, 1024>>>(Wp);
    prep_wt_kernel<<<NTOT*D_/256, 256>>>(Wq, Wk, Wv);
    qkv_mma_kernel<<<M_/64, 256>>>(x);
    flash_attn_kernel<<<dim3(T_/64, B_), 128>>>();
    proj_kernel<<<dim3(M_/64, D_/64), 256>>>(bp, out);

    (void)in_sizes; (void)n_in; (void)out_size;
}